// round 1
// baseline (speedup 1.0000x reference)
#include <cuda_runtime.h>
#include <cuda_bf16.h>
#include <math.h>

#define BB 2
#define LL 2048
#define DD 1024
#define HH 16
#define DK 64
#define NEGV (-1000000000.0f)
#define EPSV 1e-6f

// ---------------- scratch (no allocations allowed) ----------------
__device__ float g_qh[(size_t)BB * HH * LL * DK];   // [b][h][l][d]
__device__ float g_kh[(size_t)BB * HH * LL * DK];
__device__ float g_vh[(size_t)BB * HH * LL * DK];
__device__ float g_ctx[(size_t)BB * LL * DD];       // [b*l][h*dv+d]
__device__ float g_tmp[(size_t)BB * LL * DD];       // pre-LN
__device__ float g_attn_fallback[1];                // placeholder (attn lives in d_out)

// =====================================================================
// NT GEMM (A row-major MxK, B row-major NxK), 128x128 tile, BK=16,
// 256 threads, 8x8 per thread.
// =====================================================================

// ---- projection: Y = X @ W^T + b, scatter to [b][h][l][64] ----
__global__ __launch_bounds__(256) void proj_gemm(
    const float* __restrict__ X, const float* __restrict__ W,
    const float* __restrict__ bias, int sel)
{
    __shared__ float As[16][128];
    __shared__ float Bs[16][128];
    const int tid = threadIdx.x;
    const int tx = tid & 15, ty = tid >> 4;
    const float* Ab = X + (size_t)(blockIdx.y * 128) * DD;
    const float* Bb = W + (size_t)(blockIdx.x * 128) * DD;
    float acc[8][8];
#pragma unroll
    for (int i = 0; i < 8; i++)
#pragma unroll
        for (int j = 0; j < 8; j++) acc[i][j] = 0.f;

    for (int k0 = 0; k0 < DD; k0 += 16) {
#pragma unroll
        for (int i = 0; i < 2; i++) {
            int idx = tid + i * 256;
            int row = idx >> 2;
            int k4  = (idx & 3) << 2;
            float4 a = *(const float4*)(Ab + (size_t)row * DD + k0 + k4);
            As[k4 + 0][row] = a.x; As[k4 + 1][row] = a.y;
            As[k4 + 2][row] = a.z; As[k4 + 3][row] = a.w;
            float4 b = *(const float4*)(Bb + (size_t)row * DD + k0 + k4);
            Bs[k4 + 0][row] = b.x; Bs[k4 + 1][row] = b.y;
            Bs[k4 + 2][row] = b.z; Bs[k4 + 3][row] = b.w;
        }
        __syncthreads();
#pragma unroll
        for (int kk = 0; kk < 16; kk++) {
            float ra[8], rb[8];
            *(float4*)&ra[0] = *(const float4*)&As[kk][ty * 8];
            *(float4*)&ra[4] = *(const float4*)&As[kk][ty * 8 + 4];
            *(float4*)&rb[0] = *(const float4*)&Bs[kk][tx * 8];
            *(float4*)&rb[4] = *(const float4*)&Bs[kk][tx * 8 + 4];
#pragma unroll
            for (int i = 0; i < 8; i++)
#pragma unroll
                for (int j = 0; j < 8; j++) acc[i][j] += ra[i] * rb[j];
        }
        __syncthreads();
    }

    float* out = (sel == 0) ? g_qh : (sel == 1) ? g_kh : g_vh;
    const int m0 = blockIdx.y * 128 + ty * 8;
    const int n0 = blockIdx.x * 128 + tx * 8;
#pragma unroll
    for (int i = 0; i < 8; i++) {
        int m = m0 + i; int b_ = m >> 11; int l = m & 2047;
#pragma unroll
        for (int j = 0; j < 8; j++) {
            int n = n0 + j; int h = n >> 6; int d = n & 63;
            out[((((size_t)b_ * HH + h) * LL + l) << 6) + d] = acc[i][j] + bias[n];
        }
    }
}

// ---- scores: S = (qh/8) @ kh^T per (b,h), raw into attn region ----
__global__ __launch_bounds__(256) void score_gemm(float* __restrict__ attn)
{
    __shared__ float As[16][128];
    __shared__ float Bs[16][128];
    const int z = blockIdx.z;                // b*H+h
    const int tid = threadIdx.x;
    const int tx = tid & 15, ty = tid >> 4;
    const float* Ab = g_qh + (size_t)z * LL * DK + (size_t)(blockIdx.y * 128) * DK;
    const float* Bb = g_kh + (size_t)z * LL * DK + (size_t)(blockIdx.x * 128) * DK;
    float acc[8][8];
#pragma unroll
    for (int i = 0; i < 8; i++)
#pragma unroll
        for (int j = 0; j < 8; j++) acc[i][j] = 0.f;

    for (int k0 = 0; k0 < DK; k0 += 16) {
#pragma unroll
        for (int i = 0; i < 2; i++) {
            int idx = tid + i * 256;
            int row = idx >> 2;
            int k4  = (idx & 3) << 2;
            float4 a = *(const float4*)(Ab + (size_t)row * DK + k0 + k4);
            As[k4 + 0][row] = a.x; As[k4 + 1][row] = a.y;
            As[k4 + 2][row] = a.z; As[k4 + 3][row] = a.w;
            float4 b = *(const float4*)(Bb + (size_t)row * DK + k0 + k4);
            Bs[k4 + 0][row] = b.x; Bs[k4 + 1][row] = b.y;
            Bs[k4 + 2][row] = b.z; Bs[k4 + 3][row] = b.w;
        }
        __syncthreads();
#pragma unroll
        for (int kk = 0; kk < 16; kk++) {
            float ra[8], rb[8];
            *(float4*)&ra[0] = *(const float4*)&As[kk][ty * 8];
            *(float4*)&ra[4] = *(const float4*)&As[kk][ty * 8 + 4];
            *(float4*)&rb[0] = *(const float4*)&Bs[kk][tx * 8];
            *(float4*)&rb[4] = *(const float4*)&Bs[kk][tx * 8 + 4];
#pragma unroll
            for (int i = 0; i < 8; i++)
#pragma unroll
                for (int j = 0; j < 8; j++) acc[i][j] += ra[i] * rb[j];
        }
        __syncthreads();
    }

    float* Cb = attn + (size_t)z * LL * LL;
    const int m0 = blockIdx.y * 128 + ty * 8;
    const int n0 = blockIdx.x * 128 + tx * 8;
#pragma unroll
    for (int i = 0; i < 8; i++) {
        float* Cr = Cb + (size_t)(m0 + i) * LL + n0;
        float4 o0 = make_float4(acc[i][0] * 0.125f, acc[i][1] * 0.125f,
                                acc[i][2] * 0.125f, acc[i][3] * 0.125f);
        float4 o1 = make_float4(acc[i][4] * 0.125f, acc[i][5] * 0.125f,
                                acc[i][6] * 0.125f, acc[i][7] * 0.125f);
        *(float4*)Cr = o0;
        *(float4*)(Cr + 4) = o1;
    }
}

// ---- softmax over keys with mask, in place ----
__global__ __launch_bounds__(256) void softmax_kernel(
    float* __restrict__ attn, const int* __restrict__ mask)
{
    const int row = blockIdx.x;          // (b*H+h)*L + q
    const int q = row & (LL - 1);
    const int b_ = row >> 15;            // row / (H*L)
    float* rowp = attn + (size_t)row * LL;
    const int* mrow = mask + ((size_t)b_ * LL + q) * LL;

    float4* r4 = (float4*)rowp;
    const int4* m4 = (const int4*)mrow;
    const int tid = threadIdx.x;
    float v[8];
    float lmax = -3.4e38f;
#pragma unroll
    for (int t = 0; t < 2; t++) {
        int idx = tid + t * 256;
        float4 s = r4[idx];
        int4 mm = m4[idx];
        float a0 = (mm.x == 0) ? NEGV : s.x;
        float a1 = (mm.y == 0) ? NEGV : s.y;
        float a2 = (mm.z == 0) ? NEGV : s.z;
        float a3 = (mm.w == 0) ? NEGV : s.w;
        v[t * 4 + 0] = a0; v[t * 4 + 1] = a1; v[t * 4 + 2] = a2; v[t * 4 + 3] = a3;
        lmax = fmaxf(lmax, fmaxf(fmaxf(a0, a1), fmaxf(a2, a3)));
    }
    __shared__ float sred[8];
    const int wid = tid >> 5, lid = tid & 31;
#pragma unroll
    for (int off = 16; off; off >>= 1)
        lmax = fmaxf(lmax, __shfl_xor_sync(0xffffffffu, lmax, off));
    if (lid == 0) sred[wid] = lmax;
    __syncthreads();
    float rmax = sred[0];
#pragma unroll
    for (int i = 1; i < 8; i++) rmax = fmaxf(rmax, sred[i]);

    float lsum = 0.f;
#pragma unroll
    for (int e = 0; e < 8; e++) { v[e] = __expf(v[e] - rmax); lsum += v[e]; }
    __syncthreads();   // done reading sred
#pragma unroll
    for (int off = 16; off; off >>= 1)
        lsum += __shfl_xor_sync(0xffffffffu, lsum, off);
    if (lid == 0) sred[wid] = lsum;
    __syncthreads();
    float rsum = 0.f;
#pragma unroll
    for (int i = 0; i < 8; i++) rsum += sred[i];
    float inv = 1.0f / rsum;

#pragma unroll
    for (int t = 0; t < 2; t++) {
        int idx = tid + t * 256;
        r4[idx] = make_float4(v[t * 4 + 0] * inv, v[t * 4 + 1] * inv,
                              v[t * 4 + 2] * inv, v[t * 4 + 3] * inv);
    }
}

// ---- ctx = attn @ vh per (b,h)  (NN GEMM, M=2048, N=64, K=2048) ----
__global__ __launch_bounds__(256) void ctx_gemm(const float* __restrict__ attn)
{
    __shared__ float As[16][128];
    __shared__ float Bs[16][64];
    const int z = blockIdx.z;
    const int b_ = z >> 4, h = z & 15;
    const int tid = threadIdx.x;
    const int tx = tid & 15, ty = tid >> 4;
    const float* Ab = attn + (size_t)z * LL * LL + (size_t)(blockIdx.y * 128) * LL;
    const float* Bb = g_vh + (size_t)z * LL * DK;
    float acc[8][4];
#pragma unroll
    for (int i = 0; i < 8; i++)
#pragma unroll
        for (int j = 0; j < 4; j++) acc[i][j] = 0.f;

    for (int k0 = 0; k0 < LL; k0 += 16) {
#pragma unroll
        for (int i = 0; i < 2; i++) {
            int idx = tid + i * 256;
            int row = idx >> 2;
            int k4  = (idx & 3) << 2;
            float4 a = *(const float4*)(Ab + (size_t)row * LL + k0 + k4);
            As[k4 + 0][row] = a.x; As[k4 + 1][row] = a.y;
            As[k4 + 2][row] = a.z; As[k4 + 3][row] = a.w;
        }
        {
            int kr = tid >> 4;
            int n4 = (tid & 15) << 2;
            *(float4*)&Bs[kr][n4] = *(const float4*)(Bb + (size_t)(k0 + kr) * DK + n4);
        }
        __syncthreads();
#pragma unroll
        for (int kk = 0; kk < 16; kk++) {
            float ra[8], rb[4];
            *(float4*)&ra[0] = *(const float4*)&As[kk][ty * 8];
            *(float4*)&ra[4] = *(const float4*)&As[kk][ty * 8 + 4];
            *(float4*)&rb[0] = *(const float4*)&Bs[kk][tx * 4];
#pragma unroll
            for (int i = 0; i < 8; i++)
#pragma unroll
                for (int j = 0; j < 4; j++) acc[i][j] += ra[i] * rb[j];
        }
        __syncthreads();
    }

    const int m0 = blockIdx.y * 128 + ty * 8;
    const int n0 = tx * 4;
#pragma unroll
    for (int i = 0; i < 8; i++) {
        size_t o = ((size_t)(b_ * LL + m0 + i)) * DD + h * 64 + n0;
        *(float4*)(g_ctx + o) = make_float4(acc[i][0], acc[i][1], acc[i][2], acc[i][3]);
    }
}

// ---- out_pre = ctx @ dense_w^T + b + residual ----
__global__ __launch_bounds__(256) void dense_gemm(
    const float* __restrict__ W, const float* __restrict__ bias,
    const float* __restrict__ resid)
{
    __shared__ float As[16][128];
    __shared__ float Bs[16][128];
    const int tid = threadIdx.x;
    const int tx = tid & 15, ty = tid >> 4;
    const float* Ab = g_ctx + (size_t)(blockIdx.y * 128) * DD;
    const float* Bb = W + (size_t)(blockIdx.x * 128) * DD;
    float acc[8][8];
#pragma unroll
    for (int i = 0; i < 8; i++)
#pragma unroll
        for (int j = 0; j < 8; j++) acc[i][j] = 0.f;

    for (int k0 = 0; k0 < DD; k0 += 16) {
#pragma unroll
        for (int i = 0; i < 2; i++) {
            int idx = tid + i * 256;
            int row = idx >> 2;
            int k4  = (idx & 3) << 2;
            float4 a = *(const float4*)(Ab + (size_t)row * DD + k0 + k4);
            As[k4 + 0][row] = a.x; As[k4 + 1][row] = a.y;
            As[k4 + 2][row] = a.z; As[k4 + 3][row] = a.w;
            float4 b = *(const float4*)(Bb + (size_t)row * DD + k0 + k4);
            Bs[k4 + 0][row] = b.x; Bs[k4 + 1][row] = b.y;
            Bs[k4 + 2][row] = b.z; Bs[k4 + 3][row] = b.w;
        }
        __syncthreads();
#pragma unroll
        for (int kk = 0; kk < 16; kk++) {
            float ra[8], rb[8];
            *(float4*)&ra[0] = *(const float4*)&As[kk][ty * 8];
            *(float4*)&ra[4] = *(const float4*)&As[kk][ty * 8 + 4];
            *(float4*)&rb[0] = *(const float4*)&Bs[kk][tx * 8];
            *(float4*)&rb[4] = *(const float4*)&Bs[kk][tx * 8 + 4];
#pragma unroll
            for (int i = 0; i < 8; i++)
#pragma unroll
                for (int j = 0; j < 8; j++) acc[i][j] += ra[i] * rb[j];
        }
        __syncthreads();
    }

    const int m0 = blockIdx.y * 128 + ty * 8;
    const int n0 = blockIdx.x * 128 + tx * 8;
#pragma unroll
    for (int i = 0; i < 8; i++) {
        int m = m0 + i;
        size_t base = (size_t)m * DD;
#pragma unroll
        for (int j = 0; j < 8; j++) {
            int n = n0 + j;
            g_tmp[base + n] = acc[i][j] + bias[n] + resid[base + n];
        }
    }
}

// ---- LayerNorm rows of g_tmp -> out ----
__global__ __launch_bounds__(256) void ln_kernel(
    const float* __restrict__ lnw, const float* __restrict__ lnb,
    float* __restrict__ out)
{
    const int row = blockIdx.x;
    const int tid = threadIdx.x;
    const float4* x4 = (const float4*)(g_tmp + (size_t)row * DD);
    float4 x = x4[tid];

    __shared__ float sred[8];
    const int wid = tid >> 5, lid = tid & 31;

    float lsum = x.x + x.y + x.z + x.w;
#pragma unroll
    for (int off = 16; off; off >>= 1) lsum += __shfl_xor_sync(0xffffffffu, lsum, off);
    if (lid == 0) sred[wid] = lsum;
    __syncthreads();
    float tot = 0.f;
#pragma unroll
    for (int i = 0; i < 8; i++) tot += sred[i];
    float mu = tot * (1.0f / DD);

    float d0 = x.x - mu, d1 = x.y - mu, d2 = x.z - mu, d3 = x.w - mu;
    float lsq = d0 * d0 + d1 * d1 + d2 * d2 + d3 * d3;
    __syncthreads();
#pragma unroll
    for (int off = 16; off; off >>= 1) lsq += __shfl_xor_sync(0xffffffffu, lsq, off);
    if (lid == 0) sred[wid] = lsq;
    __syncthreads();
    float tot2 = 0.f;
#pragma unroll
    for (int i = 0; i < 8; i++) tot2 += sred[i];
    float var = tot2 * (1.0f / DD);
    float sc = rsqrtf(var + EPSV);

    const float4 w = ((const float4*)lnw)[tid];
    const float4 b = ((const float4*)lnb)[tid];
    float4 o = make_float4(d0 * sc * w.x + b.x, d1 * sc * w.y + b.y,
                           d2 * sc * w.z + b.z, d3 * sc * w.w + b.w);
    ((float4*)(out + (size_t)row * DD))[tid] = o;
}

// =====================================================================
extern "C" void kernel_launch(void* const* d_in, const int* in_sizes, int n_in,
                              void* d_out, int out_size)
{
    const float* q    = (const float*)d_in[0];
    const float* k    = (const float*)d_in[1];
    const float* v    = (const float*)d_in[2];
    const int*   mask = (const int*)d_in[3];
    const float* wq_w = (const float*)d_in[4];
    const float* wq_b = (const float*)d_in[5];
    const float* wk_w = (const float*)d_in[6];
    const float* wk_b = (const float*)d_in[7];
    const float* wv_w = (const float*)d_in[8];
    const float* wv_b = (const float*)d_in[9];
    const float* dw   = (const float*)d_in[10];
    const float* db   = (const float*)d_in[11];
    const float* lnw  = (const float*)d_in[12];
    const float* lnb  = (const float*)d_in[13];

    float* out0 = (float*)d_out;
    float* attn = out0 + (size_t)BB * LL * DD;   // tuple order: (out, attn_weights)

    proj_gemm<<<dim3(8, 32), 256>>>(q, wq_w, wq_b, 0);
    proj_gemm<<<dim3(8, 32), 256>>>(k, wk_w, wk_b, 1);
    proj_gemm<<<dim3(8, 32), 256>>>(v, wv_w, wv_b, 2);
    score_gemm<<<dim3(16, 16, 32), 256>>>(attn);
    softmax_kernel<<<BB * HH * LL, 256>>>(attn, mask);
    ctx_gemm<<<dim3(1, 16, 32), 256>>>(attn);
    dense_gemm<<<dim3(8, 32), 256>>>(dw, db, q);
    ln_kernel<<<BB * LL, 256>>>(lnw, lnb, out0);
}

// round 3
// speedup vs baseline: 2.2301x; 2.2301x over previous
#include <cuda_runtime.h>
#include <cstdint>

#define BB 2
#define LL 2048
#define DD 1024
#define HH 16
#define NEGV (-1000000000.0f)
#define EPSV 1e-6f

// ---------------- scratch (no allocations allowed) ----------------
__device__ float g_q4[(size_t)BB * LL * DD];       // Q proj, pre-scaled by 1/8
__device__ float g_k4[(size_t)BB * LL * DD];       // K proj
__device__ float g_vt[(size_t)BB * HH * 64 * LL];  // V proj transposed [b][h][d][l]
__device__ float g_ctx[(size_t)BB * LL * DD];      // ctx
__device__ float g_tmp[(size_t)BB * LL * DD];      // V natural, then pre-LN

// ---------------- tf32 helpers ----------------
__device__ __forceinline__ uint32_t f2tf(float f) {
    uint32_t u;
    asm("cvt.rna.tf32.f32 %0, %1;" : "=r"(u) : "f"(f));
    return u;
}

__device__ __forceinline__ void mma8(float* c, const uint32_t* a, const uint32_t* b) {
    asm volatile(
        "mma.sync.aligned.m16n8k8.row.col.f32.tf32.tf32.f32 "
        "{%0,%1,%2,%3}, {%4,%5,%6,%7}, {%8,%9}, {%0,%1,%2,%3};"
        : "+f"(c[0]), "+f"(c[1]), "+f"(c[2]), "+f"(c[3])
        : "r"(a[0]), "r"(a[1]), "r"(a[2]), "r"(a[3]), "r"(b[0]), "r"(b[1]));
}

// =====================================================================
// NT GEMM core: C[128 x NROWS] += A[128 x K] * B[NROWS x K]^T
// 256 threads, 8 warps (4 M x 2 N), warp tile 32 x NROWS/2.
// BK=16, double-buffered smem, row pad to 20 floats (conflict-free frags).
// =====================================================================
template <int NROWS>
__device__ __forceinline__ void gemm_tc(const float* __restrict__ A, int lda,
                                        const float* __restrict__ B, int ldb,
                                        int K, float acc[2][NROWS / 16][4]) {
    constexpr int NT = NROWS / 16;        // n-tiles per warp
    constexpr int BT = NROWS / 64;        // B float4 loads per thread
    __shared__ float As[2][128 * 20];
    __shared__ float Bs[2][NROWS * 20];

    const int tid = threadIdx.x;
    const int lane = tid & 31, w = tid >> 5;
    const int m_base = (w & 3) * 32;
    const int n_base = (w >> 2) * (NROWS / 2);
    const int gr = lane >> 2, tq = lane & 3;

#pragma unroll
    for (int i = 0; i < 2; i++)
#pragma unroll
        for (int j = 0; j < NT; j++)
#pragma unroll
            for (int r = 0; r < 4; r++) acc[i][j][r] = 0.f;

    const int S = K >> 4;
    float4 ra[2], rb[BT];

    const int arow = tid >> 2, ac4 = tid & 3;

    // prologue: tile 0
#pragma unroll
    for (int t = 0; t < 2; t++) {
        int idx = tid + t * 256;
        ra[t] = *(const float4*)(A + (size_t)(idx >> 2) * lda + ((idx & 3) << 2));
    }
#pragma unroll
    for (int t = 0; t < BT; t++) {
        int idx = tid + t * 256;
        rb[t] = *(const float4*)(B + (size_t)(idx >> 2) * ldb + ((idx & 3) << 2));
    }
#pragma unroll
    for (int t = 0; t < 2; t++) {
        int idx = tid + t * 256;
        *(float4*)&As[0][(idx >> 2) * 20 + ((idx & 3) << 2)] = ra[t];
    }
#pragma unroll
    for (int t = 0; t < BT; t++) {
        int idx = tid + t * 256;
        *(float4*)&Bs[0][(idx >> 2) * 20 + ((idx & 3) << 2)] = rb[t];
    }
    __syncthreads();

    for (int s = 0; s < S; s++) {
        const int cur = s & 1;
        if (s + 1 < S) {
            const int k0 = (s + 1) << 4;
#pragma unroll
            for (int t = 0; t < 2; t++) {
                int idx = tid + t * 256;
                ra[t] = *(const float4*)(A + (size_t)(idx >> 2) * lda + k0 + ((idx & 3) << 2));
            }
#pragma unroll
            for (int t = 0; t < BT; t++) {
                int idx = tid + t * 256;
                rb[t] = *(const float4*)(B + (size_t)(idx >> 2) * ldb + k0 + ((idx & 3) << 2));
            }
        }

        // compute on buffer `cur`
#pragma unroll
        for (int kk = 0; kk < 16; kk += 8) {
            uint32_t af[2][4], bf[NT][2];
#pragma unroll
            for (int i = 0; i < 2; i++) {
                const float* ap = &As[cur][(m_base + i * 16) * 20 + kk];
                af[i][0] = f2tf(ap[gr * 20 + tq]);
                af[i][1] = f2tf(ap[(gr + 8) * 20 + tq]);
                af[i][2] = f2tf(ap[gr * 20 + tq + 4]);
                af[i][3] = f2tf(ap[(gr + 8) * 20 + tq + 4]);
            }
#pragma unroll
            for (int j = 0; j < NT; j++) {
                const float* bp = &Bs[cur][(n_base + j * 8 + gr) * 20 + kk + tq];
                bf[j][0] = f2tf(bp[0]);
                bf[j][1] = f2tf(bp[4]);
            }
#pragma unroll
            for (int i = 0; i < 2; i++)
#pragma unroll
                for (int j = 0; j < NT; j++) mma8(acc[i][j], af[i], bf[j]);
        }

        if (s + 1 < S) {
            const int nxt = cur ^ 1;
#pragma unroll
            for (int t = 0; t < 2; t++) {
                int idx = tid + t * 256;
                *(float4*)&As[nxt][(idx >> 2) * 20 + ((idx & 3) << 2)] = ra[t];
            }
#pragma unroll
            for (int t = 0; t < BT; t++) {
                int idx = tid + t * 256;
                *(float4*)&Bs[nxt][(idx >> 2) * 20 + ((idx & 3) << 2)] = rb[t];
            }
        }
        __syncthreads();
    }
    (void)arow; (void)ac4;
}

// ---------------- projection: out = X @ W^T + b (times scale) ----------------
__global__ __launch_bounds__(256) void k_proj(const float* __restrict__ X,
                                              const float* __restrict__ W,
                                              const float* __restrict__ bias,
                                              float scale, int sel) {
    float acc[2][8][4];
    const float* A = X + (size_t)blockIdx.y * 128 * DD;
    const float* Bp = W + (size_t)blockIdx.x * 128 * DD;
    gemm_tc<128>(A, DD, Bp, DD, DD, acc);

    float* out = (sel == 0) ? g_q4 : (sel == 1) ? g_k4 : g_tmp;
    const int lane = threadIdx.x & 31, w = threadIdx.x >> 5;
    const int m0 = blockIdx.y * 128 + (w & 3) * 32;
    const int n0 = blockIdx.x * 128 + (w >> 2) * 64;
    const int gr = lane >> 2, tq = lane & 3;
#pragma unroll
    for (int i = 0; i < 2; i++) {
        const int r0 = m0 + i * 16 + gr;
#pragma unroll
        for (int j = 0; j < 8; j++) {
            const int col = n0 + j * 8 + tq * 2;
            const float b0 = bias[col], b1 = bias[col + 1];
            *(float2*)(out + (size_t)r0 * DD + col) =
                make_float2((acc[i][j][0] + b0) * scale, (acc[i][j][1] + b1) * scale);
            *(float2*)(out + (size_t)(r0 + 8) * DD + col) =
                make_float2((acc[i][j][2] + b0) * scale, (acc[i][j][3] + b1) * scale);
        }
    }
}

// ---------------- transpose V: g_tmp [b*l][h*64+d] -> g_vt [b][h][d][l] ----------------
__global__ __launch_bounds__(256) void k_trans() {
    __shared__ float t[32][33];
    const int b = blockIdx.z >> 4, h = blockIdx.z & 15;
    const int l0 = blockIdx.x * 32, d0 = blockIdx.y * 32;
    for (int i = threadIdx.y; i < 32; i += 8)
        t[i][threadIdx.x] =
            g_tmp[(size_t)(b * LL + l0 + i) * DD + h * 64 + d0 + threadIdx.x];
    __syncthreads();
    for (int i = threadIdx.y; i < 32; i += 8)
        g_vt[((size_t)((b * HH + h) * 64) + d0 + i) * LL + l0 + threadIdx.x] =
            t[threadIdx.x][i];
}

// ---------------- scores: attn[z] = qh[z] @ kh[z]^T ----------------
__global__ __launch_bounds__(256) void k_score(float* __restrict__ attn) {
    float acc[2][8][4];
    const int z = blockIdx.z, b_ = z >> 4, h = z & 15;
    const float* A = g_q4 + (size_t)b_ * LL * DD + h * 64 + (size_t)blockIdx.y * 128 * DD;
    const float* Bp = g_k4 + (size_t)b_ * LL * DD + h * 64 + (size_t)blockIdx.x * 128 * DD;
    gemm_tc<128>(A, DD, Bp, DD, 64, acc);

    float* Cb = attn + (size_t)z * LL * LL;
    const int lane = threadIdx.x & 31, w = threadIdx.x >> 5;
    const int m0 = blockIdx.y * 128 + (w & 3) * 32;
    const int n0 = blockIdx.x * 128 + (w >> 2) * 64;
    const int gr = lane >> 2, tq = lane & 3;
#pragma unroll
    for (int i = 0; i < 2; i++) {
        const int r0 = m0 + i * 16 + gr;
#pragma unroll
        for (int j = 0; j < 8; j++) {
            const int col = n0 + j * 8 + tq * 2;
            *(float2*)(Cb + (size_t)r0 * LL + col) = make_float2(acc[i][j][0], acc[i][j][1]);
            *(float2*)(Cb + (size_t)(r0 + 8) * LL + col) = make_float2(acc[i][j][2], acc[i][j][3]);
        }
    }
}

// ---------------- ctx: g_ctx = attn[z] @ vt[z]^T ----------------
__global__ __launch_bounds__(256) void k_ctx(const float* __restrict__ attn) {
    float acc[2][4][4];
    const int z = blockIdx.z, b_ = z >> 4, h = z & 15;
    const float* A = attn + (size_t)z * LL * LL + (size_t)blockIdx.y * 128 * LL;
    const float* Bp = g_vt + (size_t)z * 64 * LL;
    gemm_tc<64>(A, LL, Bp, LL, LL, acc);

    const int lane = threadIdx.x & 31, w = threadIdx.x >> 5;
    const int m0 = blockIdx.y * 128 + (w & 3) * 32;
    const int n0 = (w >> 2) * 32;
    const int gr = lane >> 2, tq = lane & 3;
#pragma unroll
    for (int i = 0; i < 2; i++) {
        const int r0 = m0 + i * 16 + gr;
#pragma unroll
        for (int j = 0; j < 4; j++) {
            const int col = n0 + j * 8 + tq * 2;
            *(float2*)(g_ctx + (size_t)(b_ * LL + r0) * DD + h * 64 + col) =
                make_float2(acc[i][j][0], acc[i][j][1]);
            *(float2*)(g_ctx + (size_t)(b_ * LL + r0 + 8) * DD + h * 64 + col) =
                make_float2(acc[i][j][2], acc[i][j][3]);
        }
    }
}

// ---------------- dense: g_tmp = ctx @ W^T + b + resid ----------------
__global__ __launch_bounds__(256) void k_dense(const float* __restrict__ W,
                                               const float* __restrict__ bias,
                                               const float* __restrict__ resid) {
    float acc[2][8][4];
    const float* A = g_ctx + (size_t)blockIdx.y * 128 * DD;
    const float* Bp = W + (size_t)blockIdx.x * 128 * DD;
    gemm_tc<128>(A, DD, Bp, DD, DD, acc);

    const int lane = threadIdx.x & 31, w = threadIdx.x >> 5;
    const int m0 = blockIdx.y * 128 + (w & 3) * 32;
    const int n0 = blockIdx.x * 128 + (w >> 2) * 64;
    const int gr = lane >> 2, tq = lane & 3;
#pragma unroll
    for (int i = 0; i < 2; i++) {
        const int r0 = m0 + i * 16 + gr;
#pragma unroll
        for (int j = 0; j < 8; j++) {
            const int col = n0 + j * 8 + tq * 2;
            const float b0 = bias[col], b1 = bias[col + 1];
            const float* R0 = resid + (size_t)r0 * DD + col;
            const float* R1 = resid + (size_t)(r0 + 8) * DD + col;
            *(float2*)(g_tmp + (size_t)r0 * DD + col) =
                make_float2(acc[i][j][0] + b0 + R0[0], acc[i][j][1] + b1 + R0[1]);
            *(float2*)(g_tmp + (size_t)(r0 + 8) * DD + col) =
                make_float2(acc[i][j][2] + b0 + R1[0], acc[i][j][3] + b1 + R1[1]);
        }
    }
}

// ---------------- softmax over keys with mask, in place ----------------
__global__ __launch_bounds__(256) void softmax_kernel(
    float* __restrict__ attn, const int* __restrict__ mask) {
    const int row = blockIdx.x;          // (b*H+h)*L + q
    const int q = row & (LL - 1);
    const int b_ = row >> 15;
    float* rowp = attn + (size_t)row * LL;
    const int* mrow = mask + ((size_t)b_ * LL + q) * LL;

    float4* r4 = (float4*)rowp;
    const int4* m4 = (const int4*)mrow;
    const int tid = threadIdx.x;
    float v[8];
    float lmax = -3.4e38f;
#pragma unroll
    for (int t = 0; t < 2; t++) {
        int idx = tid + t * 256;
        float4 s = r4[idx];
        int4 mm = m4[idx];
        float a0 = (mm.x == 0) ? NEGV : s.x;
        float a1 = (mm.y == 0) ? NEGV : s.y;
        float a2 = (mm.z == 0) ? NEGV : s.z;
        float a3 = (mm.w == 0) ? NEGV : s.w;
        v[t * 4 + 0] = a0; v[t * 4 + 1] = a1; v[t * 4 + 2] = a2; v[t * 4 + 3] = a3;
        lmax = fmaxf(lmax, fmaxf(fmaxf(a0, a1), fmaxf(a2, a3)));
    }
    __shared__ float sred[8];
    const int wid = tid >> 5, lid = tid & 31;
#pragma unroll
    for (int off = 16; off; off >>= 1)
        lmax = fmaxf(lmax, __shfl_xor_sync(0xffffffffu, lmax, off));
    if (lid == 0) sred[wid] = lmax;
    __syncthreads();
    float rmax = sred[0];
#pragma unroll
    for (int i = 1; i < 8; i++) rmax = fmaxf(rmax, sred[i]);

    float lsum = 0.f;
#pragma unroll
    for (int e = 0; e < 8; e++) { v[e] = __expf(v[e] - rmax); lsum += v[e]; }
    __syncthreads();
#pragma unroll
    for (int off = 16; off; off >>= 1)
        lsum += __shfl_xor_sync(0xffffffffu, lsum, off);
    if (lid == 0) sred[wid] = lsum;
    __syncthreads();
    float rsum = 0.f;
#pragma unroll
    for (int i = 0; i < 8; i++) rsum += sred[i];
    float inv = 1.0f / rsum;

#pragma unroll
    for (int t = 0; t < 2; t++) {
        int idx = tid + t * 256;
        r4[idx] = make_float4(v[t * 4 + 0] * inv, v[t * 4 + 1] * inv,
                              v[t * 4 + 2] * inv, v[t * 4 + 3] * inv);
    }
}

// ---------------- LayerNorm ----------------
__global__ __launch_bounds__(256) void ln_kernel(
    const float* __restrict__ lnw, const float* __restrict__ lnb,
    float* __restrict__ out) {
    const int row = blockIdx.x;
    const int tid = threadIdx.x;
    const float4* x4 = (const float4*)(g_tmp + (size_t)row * DD);
    float4 x = x4[tid];

    __shared__ float sred[8];
    const int wid = tid >> 5, lid = tid & 31;

    float lsum = x.x + x.y + x.z + x.w;
#pragma unroll
    for (int off = 16; off; off >>= 1) lsum += __shfl_xor_sync(0xffffffffu, lsum, off);
    if (lid == 0) sred[wid] = lsum;
    __syncthreads();
    float tot = 0.f;
#pragma unroll
    for (int i = 0; i < 8; i++) tot += sred[i];
    float mu = tot * (1.0f / DD);

    float d0 = x.x - mu, d1 = x.y - mu, d2 = x.z - mu, d3 = x.w - mu;
    float lsq = d0 * d0 + d1 * d1 + d2 * d2 + d3 * d3;
    __syncthreads();
#pragma unroll
    for (int off = 16; off; off >>= 1) lsq += __shfl_xor_sync(0xffffffffu, lsq, off);
    if (lid == 0) sred[wid] = lsq;
    __syncthreads();
    float tot2 = 0.f;
#pragma unroll
    for (int i = 0; i < 8; i++) tot2 += sred[i];
    float var = tot2 * (1.0f / DD);
    float sc = rsqrtf(var + EPSV);

    const float4 w = ((const float4*)lnw)[tid];
    const float4 b = ((const float4*)lnb)[tid];
    float4 o = make_float4(d0 * sc * w.x + b.x, d1 * sc * w.y + b.y,
                           d2 * sc * w.z + b.z, d3 * sc * w.w + b.w);
    ((float4*)(out + (size_t)row * DD))[tid] = o;
}

// =====================================================================
extern "C" void kernel_launch(void* const* d_in, const int* in_sizes, int n_in,
                              void* d_out, int out_size) {
    const float* q    = (const float*)d_in[0];
    const float* k    = (const float*)d_in[1];
    const float* v    = (const float*)d_in[2];
    const int*   mask = (const int*)d_in[3];
    const float* wq_w = (const float*)d_in[4];
    const float* wq_b = (const float*)d_in[5];
    const float* wk_w = (const float*)d_in[6];
    const float* wk_b = (const float*)d_in[7];
    const float* wv_w = (const float*)d_in[8];
    const float* wv_b = (const float*)d_in[9];
    const float* dw   = (const float*)d_in[10];
    const float* db   = (const float*)d_in[11];
    const float* lnw  = (const float*)d_in[12];
    const float* lnb  = (const float*)d_in[13];

    float* out0 = (float*)d_out;
    float* attn = out0 + (size_t)BB * LL * DD;   // tuple order: (out, attn_weights)

    k_proj<<<dim3(8, 32), 256>>>(q, wq_w, wq_b, 0.125f, 0);
    k_proj<<<dim3(8, 32), 256>>>(k, wk_w, wk_b, 1.0f, 1);
    k_proj<<<dim3(8, 32), 256>>>(v, wv_w, wv_b, 1.0f, 2);
    k_trans<<<dim3(64, 2, 32), dim3(32, 8)>>>();
    k_score<<<dim3(16, 16, 32), 256>>>(attn);
    softmax_kernel<<<BB * HH * LL, 256>>>(attn, mask);
    k_ctx<<<dim3(1, 16, 32), 256>>>(attn);
    k_dense<<<dim3(8, 32), 256>>>(dw, db, q);
    ln_kernel<<<BB * LL, 256>>>(lnw, lnb, out0);
}